// round 2
// baseline (speedup 1.0000x reference)
#include <cuda_runtime.h>
#include <math.h>

#define Bn 32
#define Ln 8192
#define Cn 64
#define Mn 64           // retained modes
#define Jn 128          // 2*Mn (cos/sin rows)
#define JG 192          // Jn + Cn (spectral + pointwise contraction)
#define NCHUNK 16
#define LCHUNK 512      // Ln / NCHUNK

// ---- scratch (device globals; no allocation allowed) ----
__device__ float g_basis[Jn * Ln];                 // [j][l]: j=2k -> cos, 2k+1 -> sin of 2*pi*k*l/L
__device__ float g_Aw[Mn * Cn * Cn];               // [k][i][o] = alpha_k * Wr[i][o][k]
__device__ float g_Bw[Mn * Cn * Cn];               // [k][i][o] = alpha_k * Wi[i][o][k]
__device__ float g_Ppart[NCHUNK * Bn * Jn * Cn];   // DFT partials [ch][b][j][c]
__device__ float g_P[Bn * Jn * Cn];                // reduced DFT  [b][j][c]
__device__ float g_G[Bn * JG * Cn];                // stage-3 B operand [b][j][o]

// ---------------------------------------------------------------------------
// Basis table: exact integer phase reduction -> theta in [0, 2*pi)
// ---------------------------------------------------------------------------
__global__ void k_basis() {
    int g = blockIdx.x * blockDim.x + threadIdx.x;   // 0 .. Mn*Ln-1
    int k = g >> 13;            // / 8192
    int l = g & (Ln - 1);
    int m = (k * l) & (Ln - 1); // exact: k*l < 2^19
    float th = (float)m * (6.2831853071795864769f / (float)Ln);
    float s, c;
    sincosf(th, &s, &c);
    g_basis[(2 * k) * Ln + l]     = c;
    g_basis[(2 * k + 1) * Ln + l] = s;
}

// ---------------------------------------------------------------------------
// Transpose spectral weights to [k][i][o] with irfft scale folded in
// ---------------------------------------------------------------------------
__global__ void k_prepW(const float* __restrict__ wr, const float* __restrict__ wi) {
    int g = blockIdx.x * blockDim.x + threadIdx.x;   // [k][i][o] flat
    int o = g & 63;
    int i = (g >> 6) & 63;
    int k = g >> 12;
    float alpha = (k == 0 ? 1.0f : 2.0f) / (float)Ln;
    int widx = (i * Cn + o) * Mn + k;                // source layout [i][o][k]
    g_Aw[g] = alpha * wr[widx];
    g_Bw[g] = alpha * wi[widx];
}

// ---------------------------------------------------------------------------
// Stage 1: truncated forward DFT as GEMM.  P[b][j][c] = sum_l basis[j][l]*x[b][l][c]
// Grid: (NCHUNK, Bn), 256 threads.  M=128, N=64, K=512 per block; partials out.
// ---------------------------------------------------------------------------
__global__ void __launch_bounds__(256) k_dft(const float* __restrict__ x) {
    int ch = blockIdx.x, b = blockIdx.y;
    int l0 = ch * LCHUNK;
    __shared__ __align__(16) float Es[Jn * 16];      // [j][ll]
    __shared__ __align__(16) float Xs[16 * Cn];      // [ll][c]
    int t  = threadIdx.x;
    int tx = t & 15, ty = t >> 4;
    int j0 = ty * 8, c0 = tx * 4;
    float acc[8][4];
#pragma unroll
    for (int r = 0; r < 8; r++)
#pragma unroll
        for (int cc = 0; cc < 4; cc++) acc[r][cc] = 0.0f;

    for (int ks = 0; ks < LCHUNK; ks += 16) {
#pragma unroll
        for (int i = 0; i < 8; i++) {                // 128x16 basis tile
            int idx = t + i * 256;
            int ll = idx & 15, j = idx >> 4;
            Es[j * 16 + ll] = g_basis[j * Ln + l0 + ks + ll];
        }
#pragma unroll
        for (int i = 0; i < 4; i++) {                // 16x64 x tile (coalesced)
            int idx = t + i * 256;
            int c = idx & 63, ll = idx >> 6;
            Xs[ll * Cn + c] = x[(b * Ln + l0 + ks + ll) * Cn + c];
        }
        __syncthreads();
#pragma unroll
        for (int ll = 0; ll < 16; ll++) {
            float av[8];
#pragma unroll
            for (int r = 0; r < 8; r++) av[r] = Es[(j0 + r) * 16 + ll];
            float4 bv = *(const float4*)&Xs[ll * Cn + c0];
#pragma unroll
            for (int r = 0; r < 8; r++) {
                acc[r][0] += av[r] * bv.x;
                acc[r][1] += av[r] * bv.y;
                acc[r][2] += av[r] * bv.z;
                acc[r][3] += av[r] * bv.w;
            }
        }
        __syncthreads();
    }
    float* dst = &g_Ppart[((ch * Bn + b) * Jn) * Cn];
#pragma unroll
    for (int r = 0; r < 8; r++) {
        float4 v = make_float4(acc[r][0], acc[r][1], acc[r][2], acc[r][3]);
        *(float4*)&dst[(j0 + r) * Cn + c0] = v;
    }
}

// Deterministic partial reduction
__global__ void k_reduceP() {
    int g = blockIdx.x * blockDim.x + threadIdx.x;   // Bn*Jn*Cn
    float s = 0.0f;
#pragma unroll
    for (int ch = 0; ch < NCHUNK; ch++)
        s += g_Ppart[ch * (Bn * Jn * Cn) + g];
    g_P[g] = s;
}

// ---------------------------------------------------------------------------
// Stage 2: per-mode complex mix.  P0=XFr, P1=-XFi (sign of sin row).
//   G[2k]   =  alpha*TFr = sum_i P0*A + P1*B
//   G[2k+1] = -alpha*TFi = sum_i P1*A - P0*B
// ---------------------------------------------------------------------------
__global__ void k_mix() {
    int k = blockIdx.x, b = blockIdx.y, o = threadIdx.x;
    __shared__ float P0[Cn], P1[Cn];
    P0[o] = g_P[(b * Jn + 2 * k) * Cn + o];
    P1[o] = g_P[(b * Jn + 2 * k + 1) * Cn + o];
    __syncthreads();
    float gr = 0.0f, gi = 0.0f;
#pragma unroll 8
    for (int i = 0; i < Cn; i++) {
        float a  = g_Aw[(k * Cn + i) * Cn + o];
        float bb = g_Bw[(k * Cn + i) * Cn + o];
        float pr = P0[i], pi = P1[i];
        gr += pr * a + pi * bb;
        gi += pi * a - pr * bb;
    }
    g_G[(b * JG + 2 * k) * Cn + o]     = gr;
    g_G[(b * JG + 2 * k + 1) * Cn + o] = gi;
}

// Fill rows 128..191 of G with pw_weight^T (per batch, for uniform stage-3 GEMM)
__global__ void k_pwfill(const float* __restrict__ pw) {
    int b = blockIdx.x, t = threadIdx.x;
#pragma unroll
    for (int i = 0; i < 16; i++) {
        int idx = t + i * 256;
        int o = idx & 63, ic = idx >> 6;
        g_G[(b * JG + Jn + ic) * Cn + o] = pw[o * Cn + ic];
    }
}

// ---------------------------------------------------------------------------
// Stage 3: fused inverse-DFT + pointwise GEMM + bias.
//   out[b][l][o] = sum_{j<192} BigA[l][j] * G[b][j][o] + bias[o]
//   BigA[l][0:128] = basis rows, BigA[l][128:192] = x[b][l][:]
// Grid: (64 l-tiles, Bn), 256 threads, tile 128(l) x 64(o), K=192.
// ---------------------------------------------------------------------------
__global__ void __launch_bounds__(256) k_out(const float* __restrict__ x,
                                             const float* __restrict__ bias,
                                             float* __restrict__ out) {
    int lt = blockIdx.x, b = blockIdx.y;
    int l0 = lt * 128;
    extern __shared__ __align__(16) float sm[];
    float* Gs = sm;                    // 192*64
    float* As = sm + JG * Cn;          // 128*17 (pad 17 -> conflict-free)
    int t  = threadIdx.x;
    int tx = t & 15, ty = t >> 4;
    int r0 = ty * 8, c0 = tx * 4;

#pragma unroll
    for (int i = 0; i < 48; i++)       // load full G[b] (12288 floats)
        Gs[t + i * 256] = g_G[b * (JG * Cn) + t + i * 256];

    float acc[8][4];
#pragma unroll
    for (int r = 0; r < 8; r++)
#pragma unroll
        for (int cc = 0; cc < 4; cc++) acc[r][cc] = 0.0f;

    for (int jc = 0; jc < JG; jc += 16) {
        if (jc < Jn) {
#pragma unroll
            for (int i = 0; i < 8; i++) {          // basis: [j][l], coalesced on l
                int idx = t + i * 256;
                int r = idx & 127, jj = idx >> 7;
                As[r * 17 + jj] = g_basis[(jc + jj) * Ln + l0 + r];
            }
        } else {
#pragma unroll
            for (int i = 0; i < 8; i++) {          // x tile: [l][c], c contiguous
                int idx = t + i * 256;
                int jj = idx & 15, r = idx >> 4;
                As[r * 17 + jj] = x[(b * Ln + l0 + r) * Cn + (jc - Jn) + jj];
            }
        }
        __syncthreads();
#pragma unroll
        for (int jj = 0; jj < 16; jj++) {
            float av[8];
#pragma unroll
            for (int r = 0; r < 8; r++) av[r] = As[(r0 + r) * 17 + jj];
            float4 bv = *(const float4*)&Gs[(jc + jj) * Cn + c0];
#pragma unroll
            for (int r = 0; r < 8; r++) {
                acc[r][0] += av[r] * bv.x;
                acc[r][1] += av[r] * bv.y;
                acc[r][2] += av[r] * bv.z;
                acc[r][3] += av[r] * bv.w;
            }
        }
        __syncthreads();
    }

    float b0 = bias[c0], b1 = bias[c0 + 1], b2 = bias[c0 + 2], b3 = bias[c0 + 3];
#pragma unroll
    for (int r = 0; r < 8; r++) {
        float4 v = make_float4(acc[r][0] + b0, acc[r][1] + b1,
                               acc[r][2] + b2, acc[r][3] + b3);
        *(float4*)&out[(b * Ln + l0 + r0 + r) * Cn + c0] = v;
    }
}

// ---------------------------------------------------------------------------
extern "C" void kernel_launch(void* const* d_in, const int* in_sizes, int n_in,
                              void* d_out, int out_size) {
    const float* x    = (const float*)d_in[0];
    const float* wr   = (const float*)d_in[1];
    const float* wi   = (const float*)d_in[2];
    const float* pw   = (const float*)d_in[3];
    const float* bias = (const float*)d_in[4];
    float* out = (float*)d_out;

    k_basis<<<(Mn * Ln) / 256, 256>>>();
    k_prepW<<<(Mn * Cn * Cn) / 256, 256>>>(wr, wi);
    k_dft<<<dim3(NCHUNK, Bn), 256>>>(x);
    k_reduceP<<<(Bn * Jn * Cn) / 256, 256>>>();
    k_mix<<<dim3(Mn, Bn), Cn>>>();
    k_pwfill<<<Bn, 256>>>(pw);

    int smem = (JG * Cn + 128 * 17) * (int)sizeof(float);   // 57856 B
    cudaFuncSetAttribute(k_out, cudaFuncAttributeMaxDynamicSharedMemorySize, smem);
    k_out<<<dim3(Ln / 128, Bn), 256, smem>>>(x, bias, out);
}